// round 8
// baseline (speedup 1.0000x reference)
#include <cuda.h>
#include <cuda_runtime.h>
#include <cuda_fp16.h>
#include <cstdint>

#define M_DIM 2048
#define N_DIM 4096
#define K_DIM 4096

// ---------------- scratch (static device globals; no runtime alloc) -------
__device__ __half   g_Wh[(size_t)N_DIM * K_DIM];   // transcribed weight, fp16
__device__ __half   g_Xh[(size_t)M_DIM * K_DIM];   // x, fp16
// 32 buckets x 64 chunks, bucket-major (buckets 256B apart -> distinct L2 lines)
__device__ uint32_t g_flags2[32 * 64];

// ---------------- PTX helpers ----------------------------------------------
__device__ __forceinline__ uint32_t smem_u32(const void* p) {
    uint32_t a;
    asm("{ .reg .u64 t; cvta.to.shared.u64 t, %1; cvt.u32.u64 %0, t; }" : "=r"(a) : "l"(p));
    return a;
}
#define MBAR_INIT(a, n) \
    asm volatile("mbarrier.init.shared.b64 [%0], %1;" :: "r"(a), "r"((uint32_t)(n)) : "memory")
#define MBAR_ARRIVE(a) \
    asm volatile("mbarrier.arrive.shared.b64 _, [%0];" :: "r"(a) : "memory")
#define MBAR_WAIT(a, ph) do {                                                   \
    uint32_t _m = (a); uint32_t _p = (ph); uint32_t _d;                         \
    asm volatile("{\n\t.reg .pred p;\n\t"                                       \
        "mbarrier.try_wait.parity.acquire.cta.shared::cta.b64 p, [%1], %2;\n\t" \
        "selp.b32 %0, 1, 0, p;\n\t}"                                            \
        : "=r"(_d) : "r"(_m), "r"(_p) : "memory");                              \
    if (!_d) {                                                                  \
        asm volatile("{\n\t.reg .pred P1;\n\t"                                  \
            "WL_%=:\n\t"                                                        \
            "mbarrier.try_wait.parity.acquire.cta.shared::cta.b64 P1, [%0], %1, 0x989680;\n\t" \
            "@P1 bra.uni WD_%=;\n\t"                                            \
            "bra.uni WL_%=;\n\t"                                                \
            "WD_%=:\n\t}" :: "r"(_m), "r"(_p) : "memory");                      \
    } } while (0)

// cp.async 16B, L2-only caching (generic proxy -> ordinary acquire/release rules)
__device__ __forceinline__ void cp16(uint32_t sdst, const void* gsrc) {
    asm volatile("cp.async.cg.shared.global [%0], [%1], 16;"
                 :: "r"(sdst), "l"(gsrc) : "memory");
}
// .noinc: do NOT bump the pending count — this lane's arrival is counted when
// all its previously-issued cp.asyncs complete. (Without .noinc the pending
// count is incremented first => net zero => the barrier never flips: R7 hang.)
#define CPASYNC_MBAR_ARRIVE_NOINC(bar) \
    asm volatile("cp.async.mbarrier.arrive.noinc.shared.b64 [%0];" :: "r"(bar) : "memory")

__device__ __forceinline__ void ldsm_x4(uint32_t (&r)[4], uint32_t addr) {
    asm volatile("ldmatrix.sync.aligned.m8n8.x4.shared.b16 {%0,%1,%2,%3}, [%4];"
        : "=r"(r[0]), "=r"(r[1]), "=r"(r[2]), "=r"(r[3]) : "r"(addr));
}
__device__ __forceinline__ void mma16816(float (&d)[4], const uint32_t (&a)[4],
                                         uint32_t b0, uint32_t b1) {
    asm volatile("mma.sync.aligned.m16n8k16.row.col.f32.f16.f16.f32 "
        "{%0,%1,%2,%3},{%4,%5,%6,%7},{%8,%9},{%0,%1,%2,%3};"
        : "+f"(d[0]), "+f"(d[1]), "+f"(d[2]), "+f"(d[3])
        : "r"(a[0]), "r"(a[1]), "r"(a[2]), "r"(a[3]), "r"(b0), "r"(b1));
}

// ---------------------------------------------------------------------------
__global__ void reset_k() {
    for (int i = threadIdx.x; i < 32 * 64; i += blockDim.x) g_flags2[i] = 0;
}

// ---------------------------------------------------------------------------
// Fused persistent kernel: 148 CTAs x 416 threads.
//   warps 0-7 : MMA, CTA tile 128x128 (warp 32x64), BK=64, 4-stage pipeline
//   warp  8   : cp.async producer (ALL 32 lanes), gated on cross-CTA flags
//   warps 9-12: fractal prep, k-chunk-major; every thread releases its own
//               writes per chunk into its lane-sharded flag bucket
// ---------------------------------------------------------------------------
#define NSTAGES 4
#define BK      64
#define A_BYTES (128 * 128)              // 16KB (128 rows x 64 halves swizzled)
#define STAGE_BYTES (2 * A_BYTES)        // 32KB
#define DYN_SMEM (NSTAGES * STAGE_BYTES + 1024)
#define NCTA    148
#define PREP_T  128
#define NTILES  512                      // (2048/128) x (4096/128)
#define NCHUNKS 64
#define W_F4    65536                    // float4s per W chunk (4096 rows x 16)
#define X_F4    32768                    // float4s per X chunk (2048 rows x 16)
#define PSTRIDE (NCTA * PREP_T)          // 18944 prep threads total
#define PER_BUCKET (NCTA * 4)            // 592 releases per bucket per chunk

__global__ void __launch_bounds__(416, 1)
fused_k(const float* __restrict__ x, const float* __restrict__ seed,
        const float* __restrict__ da, const float* __restrict__ db,
        int niter,
        const float* __restrict__ bias, float* __restrict__ out) {
    extern __shared__ char dsm[];
    __shared__ uint64_t bars[2 * NSTAGES];   // full[0..3], empty[0..3]
    __shared__ float s_a[32], s_b[32];

    const uint32_t tiles_s = (smem_u32(dsm) + 1023u) & ~1023u;
    const uint32_t bar0 = smem_u32(bars);
    const int tid = threadIdx.x;
    const int wid = tid >> 5;
    const int lane = tid & 31;

    if (tid == 0) {
        #pragma unroll
        for (int s = 0; s < NSTAGES; s++) {
            MBAR_INIT(bar0 + s * 8, 32);              // full: 32 producer lanes
            MBAR_INIT(bar0 + (NSTAGES + s) * 8, 8);   // empty: 8 MMA warps
        }
    }
    if (tid >= 288 && tid < 288 + 32) {
        int k = tid - 288;
        s_a[k] = (k < niter) ? da[k] : 0.f;
        s_b[k] = (k < niter) ? db[k] : 0.f;
    }
    __syncthreads();

    // ===================== PREP warps (9..12) =====================
    if (wid >= 9) {
        const int ptid = blockIdx.x * PREP_T + (tid - 288);
        uint32_t* myflag = g_flags2 + lane * 64;   // this thread's bucket row
        const float4* s4 = reinterpret_cast<const float4*>(seed);
        const float4* x4 = reinterpret_cast<const float4*>(x);
        for (int c = 0; c < NCHUNKS; c++) {
            for (int idx = ptid; idx < W_F4; idx += PSTRIDE) {
                const int r = idx >> 4, j = idx & 15;
                float4 w = s4[(size_t)r * 1024 + c * 16 + j];
                #pragma unroll 20
                for (int k = 0; k < niter; k++) {
                    const float a = s_a[k], b = s_b[k];
                    w.x = fmaf(b, __sinf(w.x), a * w.x);
                    w.y = fmaf(b, __sinf(w.y), a * w.y);
                    w.z = fmaf(b, __sinf(w.z), a * w.z);
                    w.w = fmaf(b, __sinf(w.w), a * w.w);
                }
                __half2 h0 = __floats2half2_rn(w.x, w.y);
                __half2 h1 = __floats2half2_rn(w.z, w.w);
                *reinterpret_cast<uint2*>(g_Wh + (size_t)r * K_DIM + c * 64 + j * 4) =
                    make_uint2(*(uint32_t*)&h0, *(uint32_t*)&h1);
            }
            for (int idx = ptid; idx < X_F4; idx += PSTRIDE) {
                const int r = idx >> 4, j = idx & 15;
                float4 v = x4[(size_t)r * 1024 + c * 16 + j];
                __half2 h0 = __floats2half2_rn(v.x, v.y);
                __half2 h1 = __floats2half2_rn(v.z, v.w);
                *reinterpret_cast<uint2*>(g_Xh + (size_t)r * K_DIM + c * 64 + j * 4) =
                    make_uint2(*(uint32_t*)&h0, *(uint32_t*)&h1);
            }
            // Per-thread release of THIS thread's chunk-c writes.
            asm volatile("red.release.gpu.global.add.u32 [%0], %1;"
                         :: "l"(myflag + c), "r"(1u) : "memory");
        }
        return;
    }

    // ===================== producer warp (8): cp.async, whole warp ==========
    if (wid == 8) {
        const int kc = lane & 7;          // 16B column within 128B row
        const int rl = lane >> 3;         // row sub-offset 0..3
        int g = 0, max_ready = -1;
        for (int w = 0; w < 4; w++) {
            const int tile = blockIdx.x + w * NCTA;
            if (tile >= NTILES) break;
            const int tm = (tile & 15) << 7;
            const int tn = (tile >> 4) << 7;
            for (int t = 0; t < NCHUNKS; t++, g++) {
                const int s = g & 3;
                if (g >= NSTAGES)
                    MBAR_WAIT(bar0 + (NSTAGES + s) * 8, ((g - NSTAGES) >> 2) & 1);
                if (t > max_ready) {
                    // Every lane acquire-polls its own bucket; __all_sync +
                    // __syncwarp propagate acquired visibility warp-wide.
                    uint32_t v; int ok;
                    do {
                        asm volatile("ld.acquire.gpu.global.u32 %0, [%1];"
                                     : "=r"(v) : "l"(g_flags2 + lane * 64 + t)
                                     : "memory");
                        ok = (v >= PER_BUCKET);
                        if (!__all_sync(0xffffffffu, ok))
                            asm volatile("nanosleep.u32 256;");
                        else break;
                    } while (true);
                    max_ready = t;
                }
                __syncwarp();
                const uint32_t st = tiles_s + s * STAGE_BYTES;
                const char* gA = (const char*)(g_Xh + (size_t)tm * K_DIM + t * 64) + kc * 16;
                const char* gB = (const char*)(g_Wh + (size_t)tn * K_DIM + t * 64) + kc * 16;
                #pragma unroll
                for (int i = 0; i < 32; i++) {
                    const int row = i * 4 + rl;
                    const uint32_t so = row * 128 + ((kc * 16) ^ ((row & 7) << 4));
                    cp16(st + so, gA + (size_t)row * (K_DIM * 2));
                }
                #pragma unroll
                for (int i = 0; i < 32; i++) {
                    const int row = i * 4 + rl;
                    const uint32_t so = row * 128 + ((kc * 16) ^ ((row & 7) << 4));
                    cp16(st + A_BYTES + so, gB + (size_t)row * (K_DIM * 2));
                }
                CPASYNC_MBAR_ARRIVE_NOINC(bar0 + s * 8);  // fires when this
                                                          // lane's copies land
            }
        }
        return;
    }

    // ===================== MMA warps (0..7) =====================
    const int wm = (wid & 3) * 32;       // {0,32,64,96}
    const int wn = (wid >> 2) * 64;      // {0,64}

    const int a_row_l = (lane & 15);
    const int a_k16   = (lane >> 4) * 16;
    const int b_row_l = (lane & 7) + ((lane >> 4) << 3);
    const int b_k16   = ((lane >> 3) & 1) * 16;

    uint32_t a_base[2], a_xor[2];
    #pragma unroll
    for (int fm = 0; fm < 2; fm++) {
        const int r = wm + fm * 16 + a_row_l;
        a_base[fm] = r * 128;
        a_xor[fm] = (r & 7) << 4;
    }
    uint32_t b_base[4], b_xor[4];
    #pragma unroll
    for (int fn = 0; fn < 4; fn++) {
        const int r = wn + fn * 16 + b_row_l;
        b_base[fn] = r * 128;
        b_xor[fn] = (r & 7) << 4;
    }

    int g = 0;
    for (int w = 0; w < 4; w++) {
        const int tile = blockIdx.x + w * NCTA;
        if (tile >= NTILES) break;
        const int tm = (tile & 15) << 7;
        const int tn = (tile >> 4) << 7;

        float acc[2][8][4];
        #pragma unroll
        for (int i = 0; i < 2; i++)
            #pragma unroll
            for (int j = 0; j < 8; j++)
                #pragma unroll
                for (int c = 0; c < 4; c++) acc[i][j][c] = 0.f;

        for (int t = 0; t < NCHUNKS; t++, g++) {
            const int s = g & 3;
            MBAR_WAIT(bar0 + s * 8, (g >> 2) & 1);
            const uint32_t sa = tiles_s + s * STAGE_BYTES;
            const uint32_t sb = sa + A_BYTES;

            #pragma unroll
            for (int ks = 0; ks < 4; ks++) {
                uint32_t af[2][4], bf[4][4];
                #pragma unroll
                for (int fm = 0; fm < 2; fm++)
                    ldsm_x4(af[fm], sa + a_base[fm] + ((ks * 32 + a_k16) ^ a_xor[fm]));
                #pragma unroll
                for (int fn = 0; fn < 4; fn++)
                    ldsm_x4(bf[fn], sb + b_base[fn] + ((ks * 32 + b_k16) ^ b_xor[fn]));
                #pragma unroll
                for (int fm = 0; fm < 2; fm++)
                    #pragma unroll
                    for (int fn = 0; fn < 4; fn++) {
                        mma16816(acc[fm][2 * fn],     af[fm], bf[fn][0], bf[fn][1]);
                        mma16816(acc[fm][2 * fn + 1], af[fm], bf[fn][2], bf[fn][3]);
                    }
            }
            __syncwarp();
            if (lane == 0) MBAR_ARRIVE(bar0 + (NSTAGES + s) * 8);
        }

        // epilogue for this tile
        const int gid4 = lane >> 2;
        const int tig  = lane & 3;
        #pragma unroll
        for (int fm = 0; fm < 2; fm++) {
            const int row = tm + wm + fm * 16 + gid4;
            #pragma unroll
            for (int fn = 0; fn < 8; fn++) {
                const int col = tn + wn + fn * 8 + tig * 2;
                const float b0 = __ldg(&bias[col]);
                const float b1 = __ldg(&bias[col + 1]);
                float2 v0 = make_float2(acc[fm][fn][0] + b0, acc[fm][fn][1] + b1);
                float2 v1 = make_float2(acc[fm][fn][2] + b0, acc[fm][fn][3] + b1);
                *reinterpret_cast<float2*>(out + (size_t)row * N_DIM + col)       = v0;
                *reinterpret_cast<float2*>(out + (size_t)(row + 8) * N_DIM + col) = v1;
            }
        }
    }
}

// ---------------------------------------------------------------------------
extern "C" void kernel_launch(void* const* d_in, const int* in_sizes, int n_in,
                              void* d_out, int out_size) {
    const float* x    = (const float*)d_in[0];   // [2048, 4096]
    const float* seed = (const float*)d_in[1];   // [4096, 4096]
    const float* da   = (const float*)d_in[2];   // [20]
    const float* db   = (const float*)d_in[3];   // [20]
    const float* bias = (const float*)d_in[4];   // [4096]
    float* out = (float*)d_out;                  // [2048, 4096]
    const int niter = in_sizes[2];

    reset_k<<<1, 256>>>();

    cudaFuncSetAttribute(fused_k, cudaFuncAttributeMaxDynamicSharedMemorySize, DYN_SMEM);
    fused_k<<<NCTA, 416, DYN_SMEM>>>(x, seed, da, db, niter, bias, out);
}

// round 9
// speedup vs baseline: 1.4640x; 1.4640x over previous
#include <cuda.h>
#include <cuda_runtime.h>
#include <cuda_fp16.h>
#include <cstdint>

#define M_DIM 2048
#define N_DIM 4096
#define K_DIM 4096

// ---------------- scratch (static device globals; no runtime alloc) -------
__device__ __half   g_Wh[(size_t)N_DIM * K_DIM];   // transcribed weight, fp16
__device__ __half   g_Xh[(size_t)M_DIM * K_DIM];   // x, fp16
// 32 buckets x 64 chunks, bucket-major (buckets 256B apart -> distinct L2 lines)
__device__ uint32_t g_flags2[32 * 64];

// ---------------- PTX helpers ----------------------------------------------
__device__ __forceinline__ uint32_t smem_u32(const void* p) {
    uint32_t a;
    asm("{ .reg .u64 t; cvta.to.shared.u64 t, %1; cvt.u32.u64 %0, t; }" : "=r"(a) : "l"(p));
    return a;
}
#define MBAR_INIT(a, n) \
    asm volatile("mbarrier.init.shared.b64 [%0], %1;" :: "r"(a), "r"((uint32_t)(n)) : "memory")
#define MBAR_ARRIVE(a) \
    asm volatile("mbarrier.arrive.shared.b64 _, [%0];" :: "r"(a) : "memory")
#define MBAR_WAIT(a, ph) do {                                                   \
    uint32_t _m = (a); uint32_t _p = (ph); uint32_t _d;                         \
    asm volatile("{\n\t.reg .pred p;\n\t"                                       \
        "mbarrier.try_wait.parity.acquire.cta.shared::cta.b64 p, [%1], %2;\n\t" \
        "selp.b32 %0, 1, 0, p;\n\t}"                                            \
        : "=r"(_d) : "r"(_m), "r"(_p) : "memory");                              \
    if (!_d) {                                                                  \
        asm volatile("{\n\t.reg .pred P1;\n\t"                                  \
            "WL_%=:\n\t"                                                        \
            "mbarrier.try_wait.parity.acquire.cta.shared::cta.b64 P1, [%0], %1, 0x989680;\n\t" \
            "@P1 bra.uni WD_%=;\n\t"                                            \
            "bra.uni WL_%=;\n\t"                                                \
            "WD_%=:\n\t}" :: "r"(_m), "r"(_p) : "memory");                      \
    } } while (0)

// cp.async 16B, L2-only caching (generic proxy -> ordinary acquire/release rules)
__device__ __forceinline__ void cp16(uint32_t sdst, const void* gsrc) {
    asm volatile("cp.async.cg.shared.global [%0], [%1], 16;"
                 :: "r"(sdst), "l"(gsrc) : "memory");
}
// .noinc: this lane's arrival fires when its prior cp.asyncs complete.
#define CPASYNC_MBAR_ARRIVE_NOINC(bar) \
    asm volatile("cp.async.mbarrier.arrive.noinc.shared.b64 [%0];" :: "r"(bar) : "memory")

__device__ __forceinline__ void ldsm_x4(uint32_t (&r)[4], uint32_t addr) {
    asm volatile("ldmatrix.sync.aligned.m8n8.x4.shared.b16 {%0,%1,%2,%3}, [%4];"
        : "=r"(r[0]), "=r"(r[1]), "=r"(r[2]), "=r"(r[3]) : "r"(addr));
}
__device__ __forceinline__ void mma16816(float (&d)[4], const uint32_t (&a)[4],
                                         uint32_t b0, uint32_t b1) {
    asm volatile("mma.sync.aligned.m16n8k16.row.col.f32.f16.f16.f32 "
        "{%0,%1,%2,%3},{%4,%5,%6,%7},{%8,%9},{%0,%1,%2,%3};"
        : "+f"(d[0]), "+f"(d[1]), "+f"(d[2]), "+f"(d[3])
        : "r"(a[0]), "r"(a[1]), "r"(a[2]), "r"(a[3]), "r"(b0), "r"(b1));
}

// ---------------------------------------------------------------------------
__global__ void reset_k() {
    for (int i = threadIdx.x; i < 32 * 64; i += blockDim.x) g_flags2[i] = 0;
}

// ---------------------------------------------------------------------------
// Fused persistent kernel: 148 CTAs x 416 threads.
//   warps 0-7 : MMA, CTA tile 128x128 (warp 32x64), BK=64, 4-stage pipeline
//   warp  8   : cp.async producer (ALL 32 lanes), gated on cross-CTA flags
//   warps 9-12: fractal prep, k-chunk-major, BATCHED loads (MLP=6) and
//               16-wide interleaved sin chains; per-thread release per chunk
// ---------------------------------------------------------------------------
#define NSTAGES 4
#define BK      64
#define A_BYTES (128 * 128)              // 16KB (128 rows x 64 halves swizzled)
#define STAGE_BYTES (2 * A_BYTES)        // 32KB
#define DYN_SMEM (NSTAGES * STAGE_BYTES + 1024)
#define NCTA    148
#define PREP_T  128
#define NTILES  512                      // (2048/128) x (4096/128)
#define NCHUNKS 64
#define W_F4    65536                    // float4s per W chunk (4096 rows x 16)
#define X_F4    32768                    // float4s per X chunk (2048 rows x 16)
#define PSTRIDE (NCTA * PREP_T)          // 18944 prep threads total
#define PER_BUCKET (NCTA * 4)            // 592 releases per bucket per chunk

__global__ void __launch_bounds__(416, 1)
fused_k(const float* __restrict__ x, const float* __restrict__ seed,
        const float* __restrict__ da, const float* __restrict__ db,
        int niter,
        const float* __restrict__ bias, float* __restrict__ out) {
    extern __shared__ char dsm[];
    __shared__ uint64_t bars[2 * NSTAGES];   // full[0..3], empty[0..3]
    __shared__ float s_a[32], s_b[32];

    const uint32_t tiles_s = (smem_u32(dsm) + 1023u) & ~1023u;
    const uint32_t bar0 = smem_u32(bars);
    const int tid = threadIdx.x;
    const int wid = tid >> 5;
    const int lane = tid & 31;

    if (tid == 0) {
        #pragma unroll
        for (int s = 0; s < NSTAGES; s++) {
            MBAR_INIT(bar0 + s * 8, 32);              // full: 32 producer lanes
            MBAR_INIT(bar0 + (NSTAGES + s) * 8, 8);   // empty: 8 MMA warps
        }
    }
    if (tid >= 288 && tid < 288 + 32) {
        int k = tid - 288;
        s_a[k] = (k < niter) ? da[k] : 0.f;
        s_b[k] = (k < niter) ? db[k] : 0.f;
    }
    __syncthreads();

    // ===================== PREP warps (9..12) =====================
    if (wid >= 9) {
        const int ptid = blockIdx.x * PREP_T + (tid - 288);
        uint32_t* myflag = g_flags2 + lane * 64;   // this thread's bucket row
        const float4* s4 = reinterpret_cast<const float4*>(seed);
        const float4* x4 = reinterpret_cast<const float4*>(x);

        // Per-thread float4 indices (fixed across chunks): clamp for tail.
        int widx[4]; bool wok[4];
        #pragma unroll
        for (int i = 0; i < 4; i++) {
            int idx = ptid + i * PSTRIDE;
            wok[i] = idx < W_F4;
            widx[i] = wok[i] ? idx : (W_F4 - 1);
        }
        int xidx[2]; bool xok[2];
        #pragma unroll
        for (int i = 0; i < 2; i++) {
            int idx = ptid + i * PSTRIDE;
            xok[i] = idx < X_F4;
            xidx[i] = xok[i] ? idx : (X_F4 - 1);
        }

        for (int c = 0; c < NCHUNKS; c++) {
            // ---- load phase: 6 independent loads in flight (MLP=6) ----
            float4 wv[4], xv[2];
            #pragma unroll
            for (int i = 0; i < 4; i++) {
                const int r = widx[i] >> 4, j = widx[i] & 15;
                wv[i] = s4[(size_t)r * 1024 + c * 16 + j];
            }
            #pragma unroll
            for (int i = 0; i < 2; i++) {
                const int r = xidx[i] >> 4, j = xidx[i] & 15;
                xv[i] = x4[(size_t)r * 1024 + c * 16 + j];
            }
            // ---- compute: 20 iterations over 16 interleaved elements ----
            for (int k = 0; k < niter; k++) {
                const float a = s_a[k], b = s_b[k];
                #pragma unroll
                for (int i = 0; i < 4; i++) {
                    wv[i].x = fmaf(b, __sinf(wv[i].x), a * wv[i].x);
                    wv[i].y = fmaf(b, __sinf(wv[i].y), a * wv[i].y);
                    wv[i].z = fmaf(b, __sinf(wv[i].z), a * wv[i].z);
                    wv[i].w = fmaf(b, __sinf(wv[i].w), a * wv[i].w);
                }
            }
            // ---- store phase ----
            #pragma unroll
            for (int i = 0; i < 4; i++) {
                if (wok[i]) {
                    const int r = widx[i] >> 4, j = widx[i] & 15;
                    __half2 h0 = __floats2half2_rn(wv[i].x, wv[i].y);
                    __half2 h1 = __floats2half2_rn(wv[i].z, wv[i].w);
                    *reinterpret_cast<uint2*>(g_Wh + (size_t)r * K_DIM + c * 64 + j * 4) =
                        make_uint2(*(uint32_t*)&h0, *(uint32_t*)&h1);
                }
            }
            #pragma unroll
            for (int i = 0; i < 2; i++) {
                if (xok[i]) {
                    const int r = xidx[i] >> 4, j = xidx[i] & 15;
                    __half2 h0 = __floats2half2_rn(xv[i].x, xv[i].y);
                    __half2 h1 = __floats2half2_rn(xv[i].z, xv[i].w);
                    *reinterpret_cast<uint2*>(g_Xh + (size_t)r * K_DIM + c * 64 + j * 4) =
                        make_uint2(*(uint32_t*)&h0, *(uint32_t*)&h1);
                }
            }
            // Per-thread release of THIS thread's chunk-c writes.
            asm volatile("red.release.gpu.global.add.u32 [%0], %1;"
                         :: "l"(myflag + c), "r"(1u) : "memory");
        }
        return;
    }

    // ===================== producer warp (8): cp.async, whole warp ==========
    if (wid == 8) {
        const int kc = lane & 7;          // 16B column within 128B row
        const int rl = lane >> 3;         // row sub-offset 0..3
        int g = 0, max_ready = -1;
        for (int w = 0; w < 4; w++) {
            const int tile = blockIdx.x + w * NCTA;
            if (tile >= NTILES) break;
            const int tm = (tile & 15) << 7;
            const int tn = (tile >> 4) << 7;
            for (int t = 0; t < NCHUNKS; t++, g++) {
                const int s = g & 3;
                if (g >= NSTAGES)
                    MBAR_WAIT(bar0 + (NSTAGES + s) * 8, ((g - NSTAGES) >> 2) & 1);
                if (t > max_ready) {
                    // Every lane acquire-polls its own bucket; __all_sync +
                    // __syncwarp propagate acquired visibility warp-wide.
                    uint32_t v; int ok;
                    do {
                        asm volatile("ld.acquire.gpu.global.u32 %0, [%1];"
                                     : "=r"(v) : "l"(g_flags2 + lane * 64 + t)
                                     : "memory");
                        ok = (v >= PER_BUCKET);
                        if (!__all_sync(0xffffffffu, ok))
                            asm volatile("nanosleep.u32 256;");
                        else break;
                    } while (true);
                    max_ready = t;
                }
                __syncwarp();
                const uint32_t st = tiles_s + s * STAGE_BYTES;
                const char* gA = (const char*)(g_Xh + (size_t)tm * K_DIM + t * 64) + kc * 16;
                const char* gB = (const char*)(g_Wh + (size_t)tn * K_DIM + t * 64) + kc * 16;
                #pragma unroll
                for (int i = 0; i < 32; i++) {
                    const int row = i * 4 + rl;
                    const uint32_t so = row * 128 + ((kc * 16) ^ ((row & 7) << 4));
                    cp16(st + so, gA + (size_t)row * (K_DIM * 2));
                }
                #pragma unroll
                for (int i = 0; i < 32; i++) {
                    const int row = i * 4 + rl;
                    const uint32_t so = row * 128 + ((kc * 16) ^ ((row & 7) << 4));
                    cp16(st + A_BYTES + so, gB + (size_t)row * (K_DIM * 2));
                }
                CPASYNC_MBAR_ARRIVE_NOINC(bar0 + s * 8);
            }
        }
        return;
    }

    // ===================== MMA warps (0..7) =====================
    const int wm = (wid & 3) * 32;       // {0,32,64,96}
    const int wn = (wid >> 2) * 64;      // {0,64}

    const int a_row_l = (lane & 15);
    const int a_k16   = (lane >> 4) * 16;
    const int b_row_l = (lane & 7) + ((lane >> 4) << 3);
    const int b_k16   = ((lane >> 3) & 1) * 16;

    uint32_t a_base[2], a_xor[2];
    #pragma unroll
    for (int fm = 0; fm < 2; fm++) {
        const int r = wm + fm * 16 + a_row_l;
        a_base[fm] = r * 128;
        a_xor[fm] = (r & 7) << 4;
    }
    uint32_t b_base[4], b_xor[4];
    #pragma unroll
    for (int fn = 0; fn < 4; fn++) {
        const int r = wn + fn * 16 + b_row_l;
        b_base[fn] = r * 128;
        b_xor[fn] = (r & 7) << 4;
    }

    int g = 0;
    for (int w = 0; w < 4; w++) {
        const int tile = blockIdx.x + w * NCTA;
        if (tile >= NTILES) break;
        const int tm = (tile & 15) << 7;
        const int tn = (tile >> 4) << 7;

        float acc[2][8][4];
        #pragma unroll
        for (int i = 0; i < 2; i++)
            #pragma unroll
            for (int j = 0; j < 8; j++)
                #pragma unroll
                for (int c = 0; c < 4; c++) acc[i][j][c] = 0.f;

        for (int t = 0; t < NCHUNKS; t++, g++) {
            const int s = g & 3;
            MBAR_WAIT(bar0 + s * 8, (g >> 2) & 1);
            const uint32_t sa = tiles_s + s * STAGE_BYTES;
            const uint32_t sb = sa + A_BYTES;

            #pragma unroll
            for (int ks = 0; ks < 4; ks++) {
                uint32_t af[2][4], bf[4][4];
                #pragma unroll
                for (int fm = 0; fm < 2; fm++)
                    ldsm_x4(af[fm], sa + a_base[fm] + ((ks * 32 + a_k16) ^ a_xor[fm]));
                #pragma unroll
                for (int fn = 0; fn < 4; fn++)
                    ldsm_x4(bf[fn], sb + b_base[fn] + ((ks * 32 + b_k16) ^ b_xor[fn]));
                #pragma unroll
                for (int fm = 0; fm < 2; fm++)
                    #pragma unroll
                    for (int fn = 0; fn < 4; fn++) {
                        mma16816(acc[fm][2 * fn],     af[fm], bf[fn][0], bf[fn][1]);
                        mma16816(acc[fm][2 * fn + 1], af[fm], bf[fn][2], bf[fn][3]);
                    }
            }
            __syncwarp();
            if (lane == 0) MBAR_ARRIVE(bar0 + (NSTAGES + s) * 8);
        }

        // epilogue for this tile
        const int gid4 = lane >> 2;
        const int tig  = lane & 3;
        #pragma unroll
        for (int fm = 0; fm < 2; fm++) {
            const int row = tm + wm + fm * 16 + gid4;
            #pragma unroll
            for (int fn = 0; fn < 8; fn++) {
                const int col = tn + wn + fn * 8 + tig * 2;
                const float b0 = __ldg(&bias[col]);
                const float b1 = __ldg(&bias[col + 1]);
                float2 v0 = make_float2(acc[fm][fn][0] + b0, acc[fm][fn][1] + b1);
                float2 v1 = make_float2(acc[fm][fn][2] + b0, acc[fm][fn][3] + b1);
                *reinterpret_cast<float2*>(out + (size_t)row * N_DIM + col)       = v0;
                *reinterpret_cast<float2*>(out + (size_t)(row + 8) * N_DIM + col) = v1;
            }
        }
    }
}

// ---------------------------------------------------------------------------
extern "C" void kernel_launch(void* const* d_in, const int* in_sizes, int n_in,
                              void* d_out, int out_size) {
    const float* x    = (const float*)d_in[0];   // [2048, 4096]
    const float* seed = (const float*)d_in[1];   // [4096, 4096]
    const float* da   = (const float*)d_in[2];   // [20]
    const float* db   = (const float*)d_in[3];   // [20]
    const float* bias = (const float*)d_in[4];   // [4096]
    float* out = (float*)d_out;                  // [2048, 4096]
    const int niter = in_sizes[2];

    reset_k<<<1, 256>>>();

    cudaFuncSetAttribute(fused_k, cudaFuncAttributeMaxDynamicSharedMemorySize, DYN_SMEM);
    fused_k<<<NCTA, 416, DYN_SMEM>>>(x, seed, da, db, niter, bias, out);
}

// round 10
// speedup vs baseline: 2.1931x; 1.4981x over previous
#include <cuda.h>
#include <cuda_runtime.h>
#include <cuda_fp16.h>
#include <cstdint>

#define M_DIM 2048
#define N_DIM 4096
#define K_DIM 4096

// ---------------- scratch (static device globals; no runtime alloc) -------
__device__ __half g_Wh[(size_t)N_DIM * K_DIM];   // transcribed weight, fp16
__device__ __half g_Xh[(size_t)M_DIM * K_DIM];   // x, fp16

// ---------------- PTX helpers ----------------------------------------------
__device__ __forceinline__ uint32_t smem_u32(const void* p) {
    uint32_t a;
    asm("{ .reg .u64 t; cvta.to.shared.u64 t, %1; cvt.u32.u64 %0, t; }" : "=r"(a) : "l"(p));
    return a;
}
#define MBAR_INIT(a, n) \
    asm volatile("mbarrier.init.shared.b64 [%0], %1;" :: "r"(a), "r"((uint32_t)(n)) : "memory")
#define MBAR_ARRIVE(a) \
    asm volatile("mbarrier.arrive.shared.b64 _, [%0];" :: "r"(a) : "memory")
#define MBAR_WAIT(a, ph) do {                                                   \
    uint32_t _m = (a); uint32_t _p = (ph); uint32_t _d;                         \
    asm volatile("{\n\t.reg .pred p;\n\t"                                       \
        "mbarrier.try_wait.parity.acquire.cta.shared::cta.b64 p, [%1], %2;\n\t" \
        "selp.b32 %0, 1, 0, p;\n\t}"                                            \
        : "=r"(_d) : "r"(_m), "r"(_p) : "memory");                              \
    if (!_d) {                                                                  \
        asm volatile("{\n\t.reg .pred P1;\n\t"                                  \
            "WL_%=:\n\t"                                                        \
            "mbarrier.try_wait.parity.acquire.cta.shared::cta.b64 P1, [%0], %1, 0x989680;\n\t" \
            "@P1 bra.uni WD_%=;\n\t"                                            \
            "bra.uni WL_%=;\n\t"                                                \
            "WD_%=:\n\t}" :: "r"(_m), "r"(_p) : "memory");                      \
    } } while (0)

__device__ __forceinline__ void cp16(uint32_t sdst, const void* gsrc) {
    asm volatile("cp.async.cg.shared.global [%0], [%1], 16;"
                 :: "r"(sdst), "l"(gsrc) : "memory");
}
#define CPASYNC_MBAR_ARRIVE_NOINC(bar) \
    asm volatile("cp.async.mbarrier.arrive.noinc.shared.b64 [%0];" :: "r"(bar) : "memory")

__device__ __forceinline__ void ldsm_x4(uint32_t (&r)[4], uint32_t addr) {
    asm volatile("ldmatrix.sync.aligned.m8n8.x4.shared.b16 {%0,%1,%2,%3}, [%4];"
        : "=r"(r[0]), "=r"(r[1]), "=r"(r[2]), "=r"(r[3]) : "r"(addr));
}
__device__ __forceinline__ void mma16816(float (&d)[4], const uint32_t (&a)[4],
                                         uint32_t b0, uint32_t b1) {
    asm volatile("mma.sync.aligned.m16n8k16.row.col.f32.f16.f16.f32 "
        "{%0,%1,%2,%3},{%4,%5,%6,%7},{%8,%9},{%0,%1,%2,%3};"
        : "+f"(d[0]), "+f"(d[1]), "+f"(d[2]), "+f"(d[3])
        : "r"(a[0]), "r"(a[1]), "r"(a[2]), "r"(a[3]), "r"(b0), "r"(b1));
}
__device__ __forceinline__ void red_f32(float* p, float v) {
    asm volatile("red.global.add.f32 [%0], %1;" :: "l"(p), "f"(v) : "memory");
}

// ---------------------------------------------------------------------------
// Kernel 1: fractal transcription of W (fp16) + fp16 round of X +
//           bias pre-init of the 68 split-K output tiles.
//   Full-occupancy grid (validated ~79us in R1/R3).
// ---------------------------------------------------------------------------
#define NW4 ((size_t)N_DIM * K_DIM / 4)          // 4,194,304
#define NX4 ((size_t)M_DIM * K_DIM / 4)          // 2,097,152
#define NSPLIT 68
#define NB4 ((size_t)NSPLIT * 4096)              // 278,528 float4 of out
#define PREP_BLOCKS ((unsigned)((NW4 + NX4 + NB4) / 256))   // 25664 exactly

__global__ void prep_k(const float* __restrict__ x, const float* __restrict__ seed,
                       const float* __restrict__ da, const float* __restrict__ db,
                       int niter, const float* __restrict__ bias,
                       float* __restrict__ out) {
    __shared__ float sa[32], sb[32];
    if (threadIdx.x < 32 && threadIdx.x < niter) {
        sa[threadIdx.x] = da[threadIdx.x];
        sb[threadIdx.x] = db[threadIdx.x];
    }
    __syncthreads();

    size_t gid = (size_t)blockIdx.x * blockDim.x + threadIdx.x;
    if (gid < NW4) {
        size_t i = gid * 4;
        float4 w = *reinterpret_cast<const float4*>(seed + i);
        #pragma unroll 20
        for (int k = 0; k < niter; k++) {
            float a = sa[k], b = sb[k];
            w.x = fmaf(b, __sinf(w.x), a * w.x);
            w.y = fmaf(b, __sinf(w.y), a * w.y);
            w.z = fmaf(b, __sinf(w.z), a * w.z);
            w.w = fmaf(b, __sinf(w.w), a * w.w);
        }
        __half2 h0 = __floats2half2_rn(w.x, w.y);
        __half2 h1 = __floats2half2_rn(w.z, w.w);
        *reinterpret_cast<uint2*>(g_Wh + i) =
            make_uint2(*(uint32_t*)&h0, *(uint32_t*)&h1);
    } else if (gid < NW4 + NX4) {
        size_t i = (gid - NW4) * 4;
        float4 v = *reinterpret_cast<const float4*>(x + i);
        __half2 h0 = __floats2half2_rn(v.x, v.y);
        __half2 h1 = __floats2half2_rn(v.z, v.w);
        *reinterpret_cast<uint2*>(g_Xh + i) =
            make_uint2(*(uint32_t*)&h0, *(uint32_t*)&h1);
    } else {
        // bias pre-init for split-K tiles 444..511 (RED.ADD epilogues land here)
        size_t u = gid - NW4 - NX4;          // 0 .. NB4-1
        const int tt   = (int)(u >> 12);     // split tile 0..67
        const int e    = (int)(u & 4095);    // float4 within 128x128 tile
        const int tile = 444 + tt;
        const int tm   = (tile & 15) << 7;
        const int tn   = (tile >> 4) << 7;
        const int row  = tm + (e >> 5);
        const int col4 = e & 31;
        const float4 b4 = reinterpret_cast<const float4*>(bias)[tn / 4 + col4];
        reinterpret_cast<float4*>(out)[(size_t)row * (N_DIM / 4) + tn / 4 + col4] = b4;
    }
}

// ---------------------------------------------------------------------------
// Kernel 2: persistent GEMM, 148 CTAs x 288 threads (8 MMA warps + producer).
//   Static schedule: 3 full-K 128x128 tiles per CTA (tiles 0..443), plus for
//   CTAs 0..135 one half-K task of tiles 444..511 (RED.ADD epilogue).
// ---------------------------------------------------------------------------
#define NSTAGES 4
#define BK      64
#define A_BYTES (128 * 128)
#define STAGE_BYTES (2 * A_BYTES)
#define DYN_SMEM (NSTAGES * STAGE_BYTES + 1024)
#define NCTA    148

__device__ __forceinline__ void task_decode(int bx, int tt, int& tm, int& tn,
                                            int& kb, int& nch, bool& use_red) {
    if (tt < 3) {
        const int tile = bx + tt * NCTA;        // 0..443
        tm = (tile & 15) << 7;
        tn = (tile >> 4) << 7;
        kb = 0; nch = 64; use_red = false;
    } else {
        const int c = (bx < NSPLIT) ? bx : bx - NSPLIT;
        const int tile = 444 + c;               // 444..511
        tm = (tile & 15) << 7;
        tn = (tile >> 4) << 7;
        kb = (bx < NSPLIT) ? 0 : 32;            // half-K split
        nch = 32; use_red = true;
    }
}

__global__ void __launch_bounds__(288, 1)
gemm_k(const float* __restrict__ bias, float* __restrict__ out) {
    extern __shared__ char dsm[];
    __shared__ uint64_t bars[2 * NSTAGES];

    const uint32_t tiles_s = (smem_u32(dsm) + 1023u) & ~1023u;
    const uint32_t bar0 = smem_u32(bars);
    const int tid = threadIdx.x;
    const int wid = tid >> 5;
    const int lane = tid & 31;
    const int bx = blockIdx.x;
    const int ntask = (bx < 2 * NSPLIT) ? 4 : 3;

    if (tid == 0) {
        #pragma unroll
        for (int s = 0; s < NSTAGES; s++) {
            MBAR_INIT(bar0 + s * 8, 32);              // full: 32 producer lanes
            MBAR_INIT(bar0 + (NSTAGES + s) * 8, 8);   // empty: 8 MMA warps
        }
    }
    __syncthreads();

    // ===================== producer warp (8) =====================
    if (wid == 8) {
        const int kc = lane & 7;
        const int rl = lane >> 3;
        int g = 0;
        for (int tt = 0; tt < ntask; tt++) {
            int tm, tn, kb, nch; bool use_red;
            task_decode(bx, tt, tm, tn, kb, nch, use_red);
            for (int t = 0; t < nch; t++, g++) {
                const int s = g & 3;
                if (g >= NSTAGES)
                    MBAR_WAIT(bar0 + (NSTAGES + s) * 8, ((g - NSTAGES) >> 2) & 1);
                const int cc = kb + t;   // global k-chunk
                const uint32_t st = tiles_s + s * STAGE_BYTES;
                const char* gA = (const char*)(g_Xh + (size_t)tm * K_DIM) + cc * 128 + kc * 16;
                const char* gB = (const char*)(g_Wh + (size_t)tn * K_DIM) + cc * 128 + kc * 16;
                #pragma unroll
                for (int i = 0; i < 32; i++) {
                    const int row = i * 4 + rl;
                    const uint32_t so = row * 128 + ((kc * 16) ^ ((row & 7) << 4));
                    cp16(st + so, gA + (size_t)row * (K_DIM * 2));
                }
                #pragma unroll
                for (int i = 0; i < 32; i++) {
                    const int row = i * 4 + rl;
                    const uint32_t so = row * 128 + ((kc * 16) ^ ((row & 7) << 4));
                    cp16(st + A_BYTES + so, gB + (size_t)row * (K_DIM * 2));
                }
                CPASYNC_MBAR_ARRIVE_NOINC(bar0 + s * 8);
            }
        }
        return;
    }

    // ===================== MMA warps (0..7) =====================
    const int wm = (wid & 3) * 32;
    const int wn = (wid >> 2) * 64;

    const int a_row_l = (lane & 15);
    const int a_k16   = (lane >> 4) * 16;
    const int b_row_l = (lane & 7) + ((lane >> 4) << 3);
    const int b_k16   = ((lane >> 3) & 1) * 16;

    uint32_t a_base[2], a_xor[2];
    #pragma unroll
    for (int fm = 0; fm < 2; fm++) {
        const int r = wm + fm * 16 + a_row_l;
        a_base[fm] = r * 128;
        a_xor[fm] = (r & 7) << 4;
    }
    uint32_t b_base[4], b_xor[4];
    #pragma unroll
    for (int fn = 0; fn < 4; fn++) {
        const int r = wn + fn * 16 + b_row_l;
        b_base[fn] = r * 128;
        b_xor[fn] = (r & 7) << 4;
    }

    int g = 0;
    for (int tt = 0; tt < ntask; tt++) {
        int tm, tn, kb, nch; bool use_red;
        task_decode(bx, tt, tm, tn, kb, nch, use_red);

        float acc[2][8][4];
        #pragma unroll
        for (int i = 0; i < 2; i++)
            #pragma unroll
            for (int j = 0; j < 8; j++)
                #pragma unroll
                for (int c = 0; c < 4; c++) acc[i][j][c] = 0.f;

        for (int t = 0; t < nch; t++, g++) {
            const int s = g & 3;
            MBAR_WAIT(bar0 + s * 8, (g >> 2) & 1);
            const uint32_t sa = tiles_s + s * STAGE_BYTES;
            const uint32_t sb = sa + A_BYTES;

            #pragma unroll
            for (int ks = 0; ks < 4; ks++) {
                uint32_t af[2][4], bf[4][4];
                #pragma unroll
                for (int fm = 0; fm < 2; fm++)
                    ldsm_x4(af[fm], sa + a_base[fm] + ((ks * 32 + a_k16) ^ a_xor[fm]));
                #pragma unroll
                for (int fn = 0; fn < 4; fn++)
                    ldsm_x4(bf[fn], sb + b_base[fn] + ((ks * 32 + b_k16) ^ b_xor[fn]));
                #pragma unroll
                for (int fm = 0; fm < 2; fm++)
                    #pragma unroll
                    for (int fn = 0; fn < 4; fn++) {
                        mma16816(acc[fm][2 * fn],     af[fm], bf[fn][0], bf[fn][1]);
                        mma16816(acc[fm][2 * fn + 1], af[fm], bf[fn][2], bf[fn][3]);
                    }
            }
            __syncwarp();
            if (lane == 0) MBAR_ARRIVE(bar0 + (NSTAGES + s) * 8);
        }

        // ---- epilogue ----
        const int gid4 = lane >> 2;
        const int tig  = lane & 3;
        if (!use_red) {
            #pragma unroll
            for (int fm = 0; fm < 2; fm++) {
                const int row = tm + wm + fm * 16 + gid4;
                #pragma unroll
                for (int fn = 0; fn < 8; fn++) {
                    const int col = tn + wn + fn * 8 + tig * 2;
                    const float b0 = __ldg(&bias[col]);
                    const float b1 = __ldg(&bias[col + 1]);
                    float2 v0 = make_float2(acc[fm][fn][0] + b0, acc[fm][fn][1] + b1);
                    float2 v1 = make_float2(acc[fm][fn][2] + b0, acc[fm][fn][3] + b1);
                    *reinterpret_cast<float2*>(out + (size_t)row * N_DIM + col)       = v0;
                    *reinterpret_cast<float2*>(out + (size_t)(row + 8) * N_DIM + col) = v1;
                }
            }
        } else {
            // half-K partial: accumulate into bias-pre-initialized region
            #pragma unroll
            for (int fm = 0; fm < 2; fm++) {
                const int row = tm + wm + fm * 16 + gid4;
                #pragma unroll
                for (int fn = 0; fn < 8; fn++) {
                    const int col = tn + wn + fn * 8 + tig * 2;
                    red_f32(out + (size_t)row * N_DIM + col,           acc[fm][fn][0]);
                    red_f32(out + (size_t)row * N_DIM + col + 1,       acc[fm][fn][1]);
                    red_f32(out + (size_t)(row + 8) * N_DIM + col,     acc[fm][fn][2]);
                    red_f32(out + (size_t)(row + 8) * N_DIM + col + 1, acc[fm][fn][3]);
                }
            }
        }
    }
}

// ---------------------------------------------------------------------------
extern "C" void kernel_launch(void* const* d_in, const int* in_sizes, int n_in,
                              void* d_out, int out_size) {
    const float* x    = (const float*)d_in[0];   // [2048, 4096]
    const float* seed = (const float*)d_in[1];   // [4096, 4096]
    const float* da   = (const float*)d_in[2];   // [20]
    const float* db   = (const float*)d_in[3];   // [20]
    const float* bias = (const float*)d_in[4];   // [4096]
    float* out = (float*)d_out;                  // [2048, 4096]
    const int niter = in_sizes[2];

    prep_k<<<PREP_BLOCKS, 256>>>(x, seed, da, db, niter, bias, out);

    cudaFuncSetAttribute(gemm_k, cudaFuncAttributeMaxDynamicSharedMemorySize, DYN_SMEM);
    gemm_k<<<NCTA, 288, DYN_SMEM>>>(bias, out);
}